// round 4
// baseline (speedup 1.0000x reference)
#include <cuda_runtime.h>
#include <cstdint>

// FieldAwareFM: B=16384, F=10 fields, D=8.
// y[b] = b_lin + sum_f w[xoff[b,f]] + sum_{f<g} <emb[f, xoff[b,g]], emb[g, xoff[b,f]]>
//
// Two kernels per launch:
//  1) pack_kernel: re-packs small fields (4..9, 8610 columns total) into
//     per-column blocks: g_pack[col][slot<9][8] = emb[f, off_c+col_local, :]
//     for the 9 fields f != c, plus w[off_c+col] at float offset 72.
//     A block = 9 rows the FFM needs together -> 3 cache lines instead of 9.
//  2) ffm_kernel: one warp per sample; 90 (pair,half) tasks; pairs sorted by
//     g DESC so same-block loads land in adjacent lanes of one LDG
//     (wavefronts = distinct 128B lines per instruction).

#define BATCH      16384
#define NUM_FIELDS 10
#define FACTOR_DIM 8
#define INPUT_DIM  188610
#define NPAIRS     45
#define NPACKCOLS  8610        // fields 4..9: 5000+2000+1000+500+100+10
#define BLK_F      80          // floats per packed block (9*8 + w + pad)

__constant__ int c_off[NUM_FIELDS] = {
    0, 100000, 150000, 170000, 180000, 185000, 187000, 188000, 188500, 188600
};
__constant__ int c_pb[6] = { 0, 5000, 7000, 8000, 8500, 8600 };  // field 4..9 pack base

__device__ __align__(128) float g_pack[NPACKCOLS * BLK_F];

// ---------------- pack kernel ----------------
__global__ __launch_bounds__(256) void pack_kernel(
    const float* __restrict__ w,
    const float* __restrict__ emb)
{
    int tid = blockIdx.x * blockDim.x + threadIdx.x;   // [0, 8610*20)
    if (tid >= NPACKCOLS * 20) return;
    int jp = tid / 20;          // packed column id
    int u  = tid % 20;          // unit within block
    int c4 = (jp >= 5000) + (jp >= 7000) + (jp >= 8000) + (jp >= 8500) + (jp >= 8600);
    int c  = 4 + c4;            // owning field
    int col = c_off[c] + (jp - c_pb[c4]);   // global column index

    if (u < 18) {
        int s = u >> 1, part = u & 1;
        int f = s + (s >= c);   // slot s holds field f (skipping c)
        const float4 v = *reinterpret_cast<const float4*>(
            emb + ((size_t)f * INPUT_DIM + (size_t)col) * FACTOR_DIM + part * 4);
        *reinterpret_cast<float4*>(g_pack + (size_t)jp * BLK_F + s * 8 + part * 4) = v;
    } else if (u == 18) {
        g_pack[(size_t)jp * BLK_F + 72] = w[col];
    }
}

// ---------------- main kernel ----------------
__global__ __launch_bounds__(256, 6) void ffm_kernel(
    const int*   __restrict__ x,       // (B, 10) int32 raw per-field indices
    const float* __restrict__ w,       // (INPUT_DIM,)
    const float* __restrict__ blin,    // scalar
    const float* __restrict__ emb,     // (10, INPUT_DIM, 8)
    float*       __restrict__ out)     // (B,)
{
    const unsigned FULL = 0xFFFFFFFFu;
    int b    = (blockIdx.x * blockDim.x + threadIdx.x) >> 5;
    int lane = threadIdx.x & 31;
    if (b >= BATCH) return;

    // Lane f (<10) owns field f. V encodes addressing:
    //   packed (f>=4): V = -(blockFloatBase + 1),  unpacked: V = global x_off.
    int   V   = 0;
    float acc = 0.0f;
    if (lane < NUM_FIELDS) {
        int xr = x[b * NUM_FIELDS + lane];
        if (lane >= 4) {
            int pb = (c_pb[lane - 4] + xr) * BLK_F;
            V   = -(pb + 1);
            acc = g_pack[pb + 72];          // w folded into the block
        } else {
            V   = xr + c_off[lane];
            acc = w[V];
        }
    }

    float4 va[3], vb[3];
    bool   valid[3];

    #pragma unroll
    for (int k = 0; k < 3; k++) {
        int  t = lane + 32 * k;             // task id, 90 valid
        bool vld = t < 2 * NPAIRS;
        int  p    = vld ? (t >> 1) : 0;     // pair id (clamped: shfl convergence)
        int  part = t & 1;

        // Pairs sorted by g DESC then f ASC. Decode via exact fp32 sqrt:
        // r = 45 - p; g = ceil((sqrt(8r+1)-1)/2); f = p - 45 + g(g+1)/2.
        int   r = NPAIRS - p;
        float s = sqrtf((float)(8 * r + 1));
        int   g = (int)ceilf((s - 1.0f) * 0.5f);
        int   f = p - NPAIRS + (g * (g + 1)) / 2;

        int vg = __shfl_sync(FULL, V, g);
        int vf = __shfl_sync(FULL, V, f);

        // A = row(f, x_g): packed iff g>=4 (slot f, since f<g)
        const float* Ap = (vg < 0)
            ? (g_pack + (-vg - 1) + f * 8)
            : (emb + ((size_t)f * INPUT_DIM + (size_t)vg) * FACTOR_DIM);
        // B = row(g, x_f): packed iff f>=4 (slot g-1, since g>f)
        const float* Bp = (vf < 0)
            ? (g_pack + (-vf - 1) + (g - 1) * 8)
            : (emb + ((size_t)g * INPUT_DIM + (size_t)vf) * FACTOR_DIM);

        valid[k] = vld;
        if (vld) {
            va[k] = *reinterpret_cast<const float4*>(Ap + part * 4);
            vb[k] = *reinterpret_cast<const float4*>(Bp + part * 4);
        }
    }

    #pragma unroll
    for (int k = 0; k < 3; k++) {
        if (valid[k]) {
            acc += va[k].x * vb[k].x + va[k].y * vb[k].y
                 + va[k].z * vb[k].z + va[k].w * vb[k].w;
        }
    }

    #pragma unroll
    for (int o = 16; o > 0; o >>= 1)
        acc += __shfl_xor_sync(FULL, acc, o);

    if (lane == 0)
        out[b] = acc + blin[0];
}

extern "C" void kernel_launch(void* const* d_in, const int* in_sizes, int n_in,
                              void* d_out, int out_size) {
    const int*   x    = (const int*)  d_in[0];
    const float* w    = (const float*)d_in[1];
    const float* blin = (const float*)d_in[2];
    const float* emb  = (const float*)d_in[3];
    float* out = (float*)d_out;

    const int pack_threads = 256;
    const int pack_blocks  = (NPACKCOLS * 20 + pack_threads - 1) / pack_threads;
    pack_kernel<<<pack_blocks, pack_threads>>>(w, emb);

    const int threads = 256;                      // 8 warps = 8 samples / block
    const int blocks  = (BATCH * 32) / threads;   // 2048
    ffm_kernel<<<blocks, threads>>>(x, w, blin, emb, out);
}